// round 13
// baseline (speedup 1.0000x reference)
#include <cuda_runtime.h>
#include <cuda_bf16.h>
#include <cstdint>

// ---------------------------------------------------------------------------
// Problem constants
// ---------------------------------------------------------------------------
constexpr int B_ = 8;
constexpr int S_ = 2048;
constexpr int D_ = 768;
constexpr int H_ = 768;
constexpr long QKV_ELEMS = (long)B_ * S_ * H_;   // 12,582,912
constexpr long SC_ELEMS  = (long)B_ * S_ * S_;   // 33,554,432

constexpr int K3_PROJ = 3 * D_;   // 2304
constexpr int K3_CTX  = 3 * S_;   // 6144

// ---------------------------------------------------------------------------
// Scratch (static device globals — allocation-free per harness rules)
// ---------------------------------------------------------------------------
__device__ float g_q[QKV_ELEMS];
__device__ float g_v[QKV_ELEMS];
__device__ float g_scores[SC_ELEMS];

__device__ __nv_bfloat16 g_xpack [(long)B_*S_*K3_PROJ];
__device__ __nv_bfloat16 g_ypack [(long)B_*S_*K3_PROJ];
__device__ __nv_bfloat16 g_wqpack[(long)H_*K3_PROJ];
__device__ __nv_bfloat16 g_wkpack[(long)H_*K3_PROJ];
__device__ __nv_bfloat16 g_wvpack[(long)H_*K3_PROJ];
__device__ __nv_bfloat16 g_qpack [(long)B_*S_*K3_PROJ];
__device__ __nv_bfloat16 g_kpack [(long)B_*S_*K3_PROJ];
__device__ __nv_bfloat16 g_upack [(long)B_*H_*K3_CTX];
__device__ __nv_bfloat16 g_ppack [(long)B_*S_*K3_CTX];

// ---------------------------------------------------------------------------
// PTX helpers (base-target instructions only)
// ---------------------------------------------------------------------------
__device__ __forceinline__ uint32_t smem_to_u32(const void* p) {
    uint32_t a;
    asm("{ .reg .u64 t; cvta.to.shared.u64 t, %1; cvt.u32.u64 %0, t; }"
        : "=r"(a) : "l"(p));
    return a;
}

#define CP_ASYNC16(dst, src) \
    asm volatile("cp.async.cg.shared.global [%0], [%1], 16;" \
                 :: "r"(dst), "l"(src) : "memory")
#define CP_COMMIT() asm volatile("cp.async.commit_group;" ::: "memory")
#define CP_WAIT(n)  asm volatile("cp.async.wait_group %0;" :: "n"(n) : "memory")

#define LDMATRIX_X4(r, addr) \
    asm volatile("ldmatrix.sync.aligned.m8n8.x4.shared.b16 {%0,%1,%2,%3}, [%4];" \
        : "=r"((r)[0]), "=r"((r)[1]), "=r"((r)[2]), "=r"((r)[3]) : "r"(addr))

__device__ __forceinline__ void mma16816(float* c, const uint32_t* a,
                                         uint32_t b0, uint32_t b1) {
    asm volatile(
        "mma.sync.aligned.m16n8k16.row.col.f32.bf16.bf16.f32 "
        "{%0,%1,%2,%3}, {%4,%5,%6,%7}, {%8,%9}, {%0,%1,%2,%3};"
        : "+f"(c[0]), "+f"(c[1]), "+f"(c[2]), "+f"(c[3])
        : "r"(a[0]), "r"(a[1]), "r"(a[2]), "r"(a[3]), "r"(b0), "r"(b1));
}

// ---------------------------------------------------------------------------
// bf16 split helpers
// ---------------------------------------------------------------------------
__device__ __forceinline__ void split2(float x, __nv_bfloat16& h, __nv_bfloat16& l) {
    h = __float2bfloat16(x);
    l = __float2bfloat16(x - __bfloat162float(h));
}
__device__ __forceinline__ uint32_t packpair(__nv_bfloat16 a, __nv_bfloat16 b) {
    __nv_bfloat162 t;
    t.x = a; t.y = b;
    return *reinterpret_cast<uint32_t*>(&t);
}

// ---------------------------------------------------------------------------
// Warp-MMA bf16 GEMM: C[M,Ntot] = Apack[M,K3] @ Bpack[Ntot,K3]^T (+bias)
// 256 threads, tile 128x128, warp tile 64x32, BK=64 (halved barrier count vs
// R8's BK=32 — tensor pipe measured 44% idle-bound on sync/skew).
// 3-stage cp.async, order: wait -> sync -> issue(kt+2) -> compute, making
// distance-2 prefetch safe with 3 buffers. ROWB=144 keeps ldmatrix
// conflict-free (r*36 mod 32 = r*4: 8 distinct banks per 8 rows).
// PACK: 0=none, 1=A-style (hi,hi,lo), 2=B-style (hi,lo,hi) -> Pout[M,3*Ntot]
// ---------------------------------------------------------------------------
constexpr int STAGES   = 3;
constexpr int BK       = 64;
constexpr int ROWB     = 144;               // 64 bf16 = 128B + 16B pad
constexpr int OPER_B   = 128 * ROWB;        // 18432 bytes per operand tile
constexpr int STG_B    = 2 * OPER_B;        // 36864 bytes per stage
constexpr int SMEM_GEMM = STAGES * STG_B;   // 110592 (2 CTAs/SM: 216KB <= 228KB)

template<int PACK, bool BIAS, bool WF32>
__global__ __launch_bounds__(256, 2)
void mm_bf16_kernel(const __nv_bfloat16* __restrict__ Apack,
                    const __nv_bfloat16* __restrict__ Bpack,
                    const float* __restrict__ bias,
                    float* __restrict__ C,
                    __nv_bfloat16* __restrict__ Pout,
                    int M, int Ntot, int K3,
                    long sA, long sB, long sC)
{
    extern __shared__ __align__(128) char dsm[];

    const int tid  = threadIdx.x;
    const int wid  = tid >> 5;
    const int lane = tid & 31;
    const long z   = blockIdx.z;
    Apack += z * sA;
    Bpack += z * sB;
    if (WF32) C += z * sC;
    const int brow = blockIdx.y * 128;
    const int bcol = blockIdx.x * 128;

    const int warp_m = (wid >> 2) * 64;   // 0 or 64
    const int warp_n = (wid & 3) * 32;    // 0,32,64,96

    const uint32_t smbase = smem_to_u32(dsm);
    const __nv_bfloat16* Ag = Apack + (long)brow * K3;
    const __nv_bfloat16* Bg = Bpack + (long)bcol * K3;

    // Per-thread load: one row (tid>>1) per operand, 64B half (tid&1), 4x16B.
    const int r0 = tid >> 1;            // 0..127
    const int hb = (tid & 1) * 64;      // byte offset of half-row

    auto issue_stage = [&](int s, int k0) {
        uint32_t sa = smbase + s * STG_B;
        uint32_t dA = sa + r0 * ROWB + hb;
        const __nv_bfloat16* ga = Ag + (long)r0 * K3 + k0 + hb / 2;
        const __nv_bfloat16* gb = Bg + (long)r0 * K3 + k0 + hb / 2;
        #pragma unroll
        for (int i = 0; i < 4; ++i) {
            CP_ASYNC16(dA + i * 16, ga + i * 8);
            CP_ASYNC16(dA + OPER_B + i * 16, gb + i * 8);
        }
    };

    float acc[4][4][4];
    #pragma unroll
    for (int i = 0; i < 4; ++i)
        #pragma unroll
        for (int j = 0; j < 4; ++j)
            #pragma unroll
            for (int t = 0; t < 4; ++t) acc[i][j][t] = 0.f;

    const int KT = K3 / BK;
    issue_stage(0, 0);       CP_COMMIT();
    issue_stage(1, BK);      CP_COMMIT();

    // precomputed fragment address components
    const int a_row = lane & 15;
    const int a_kof = (lane >> 4) * 8;
    const int b_row = ((lane >> 4) & 1) * 8 + (lane & 7);
    const int b_kof = ((lane >> 3) & 1) * 8;

    int sc_ = 0;   // compute stage
    int sp_ = 2;   // issue target = (kt+2) mod 3 = (kt-1) mod 3
    for (int kt = 0; kt < KT; ++kt) {
        CP_WAIT(1);                 // group kt complete -> stage sc_ ready
        __syncthreads();            // visibility; also fences readers of sp_
        // issue stage kt+2 into buffer sp_ (readers finished pre-sync)
        if (kt + 2 < KT) issue_stage(sp_, (kt + 2) * BK);
        CP_COMMIT();                // unconditional: keeps wait-count invariant

        const uint32_t sa = smbase + sc_ * STG_B;
        #pragma unroll
        for (int kk = 0; kk < 4; ++kk) {
            uint32_t a[4][4], b[2][4];
            #pragma unroll
            for (int i = 0; i < 4; ++i) {
                uint32_t addr = sa + (warp_m + i * 16 + a_row) * ROWB
                              + (kk * 16 + a_kof) * 2;
                LDMATRIX_X4(a[i], addr);
            }
            #pragma unroll
            for (int p = 0; p < 2; ++p) {
                uint32_t addr = sa + OPER_B
                              + (warp_n + p * 16 + b_row) * ROWB
                              + (kk * 16 + b_kof) * 2;
                LDMATRIX_X4(b[p], addr);
            }
            #pragma unroll
            for (int i = 0; i < 4; ++i)
                #pragma unroll
                for (int j = 0; j < 4; ++j)
                    mma16816(acc[i][j], a[i],
                             b[j >> 1][(j & 1) * 2], b[j >> 1][(j & 1) * 2 + 1]);
        }
        sp_ = sc_;
        sc_ = (sc_ == 2) ? 0 : sc_ + 1;
    }

    // ---- epilogue ----
    const int rr = lane >> 2;          // 0..7
    const int cc = (lane & 3) * 2;     // 0,2,4,6
    #pragma unroll
    for (int j = 0; j < 4; ++j) {
        const int col = bcol + warp_n + j * 8 + cc;
        float bb0 = 0.f, bb1 = 0.f;
        if (BIAS) { bb0 = bias[col]; bb1 = bias[col + 1]; }
        #pragma unroll
        for (int i = 0; i < 4; ++i) {
            const int row0 = brow + warp_m + i * 16 + rr;
            #pragma unroll
            for (int h = 0; h < 2; ++h) {          // h=0: rows rr, h=1: rr+8
                const int r = row0 + h * 8;
                float v0 = acc[i][j][h * 2 + 0] + bb0;
                float v1 = acc[i][j][h * 2 + 1] + bb1;
                if (WF32) {
                    float2 f2; f2.x = v0; f2.y = v1;
                    *(float2*)(C + (long)r * Ntot + col) = f2;
                }
                if (PACK != 0) {
                    __nv_bfloat16 h0, l0, h1, l1;
                    split2(v0, h0, l0);
                    split2(v1, h1, l1);
                    uint32_t hp = packpair(h0, h1);
                    uint32_t lp = packpair(l0, l1);
                    __nv_bfloat16* rp = Pout + (long)r * 3 * Ntot + col;
                    if (PACK == 1) {   // A-style: hi, hi, lo
                        *(uint32_t*)(rp)            = hp;
                        *(uint32_t*)(rp + Ntot)     = hp;
                        *(uint32_t*)(rp + 2 * Ntot) = lp;
                    } else {           // B-style: hi, lo, hi
                        *(uint32_t*)(rp)            = hp;
                        *(uint32_t*)(rp + Ntot)     = lp;
                        *(uint32_t*)(rp + 2 * Ntot) = hp;
                    }
                }
            }
        }
    }
}

// ---------------------------------------------------------------------------
// pack_ab: fused A-pack for x AND y (grid.z selects). fp32 [R,768] ->
// bf16 [R,2304] chunks (hi, hi, lo).
// ---------------------------------------------------------------------------
__global__ void pack_ab(const float* __restrict__ x, const float* __restrict__ y,
                        __nv_bfloat16* __restrict__ xp, __nv_bfloat16* __restrict__ yp,
                        long n4)
{
    long i = (long)blockIdx.x * blockDim.x + threadIdx.x;
    if (i >= n4) return;
    const float* src = blockIdx.z ? y : x;
    __nv_bfloat16* dst = blockIdx.z ? yp : xp;
    float4 f = ((const float4*)src)[i];
    long e = i * 4;
    long r = e / D_;
    int  c = (int)(e % D_);
    __nv_bfloat16 h0, l0, h1, l1, h2, l2, h3, l3;
    split2(f.x, h0, l0); split2(f.y, h1, l1);
    split2(f.z, h2, l2); split2(f.w, h3, l3);
    uint2 hp = make_uint2(packpair(h0, h1), packpair(h2, h3));
    uint2 lp = make_uint2(packpair(l0, l1), packpair(l2, l3));
    __nv_bfloat16* rp = dst + r * (long)K3_PROJ + c;
    *(uint2*)(rp)          = hp;
    *(uint2*)(rp + D_)     = hp;
    *(uint2*)(rp + 2 * D_) = lp;
}

// ---------------------------------------------------------------------------
// pack_w: fused weight pack for Wq/Wk/Wv (grid.z selects).
// W [D,H] fp32 -> Wpack [H, 3D] bf16, B-style (hi, lo, hi), transposed.
// grid (H/32, D/32, 3), block (32, 8)
// ---------------------------------------------------------------------------
__global__ void pack_w(const float* __restrict__ Wq, const float* __restrict__ Wk,
                       const float* __restrict__ Wv,
                       __nv_bfloat16* __restrict__ wqp, __nv_bfloat16* __restrict__ wkp,
                       __nv_bfloat16* __restrict__ wvp)
{
    const float* W = blockIdx.z == 0 ? Wq : (blockIdx.z == 1 ? Wk : Wv);
    __nv_bfloat16* dst = blockIdx.z == 0 ? wqp : (blockIdx.z == 1 ? wkp : wvp);
    __shared__ float tile[32][33];
    const int n0 = blockIdx.x * 32;   // H dim (output rows)
    const int c0 = blockIdx.y * 32;   // D dim (k index)
    #pragma unroll
    for (int ry = 0; ry < 4; ++ry) {
        int c = c0 + threadIdx.y + ry * 8;
        tile[threadIdx.y + ry * 8][threadIdx.x] = W[(long)c * H_ + n0 + threadIdx.x];
    }
    __syncthreads();
    #pragma unroll
    for (int ry = 0; ry < 4; ++ry) {
        int n = n0 + threadIdx.y + ry * 8;
        int c = c0 + threadIdx.x;
        float val = tile[threadIdx.x][threadIdx.y + ry * 8];
        __nv_bfloat16 h, l;
        split2(val, h, l);
        __nv_bfloat16* rp = dst + (long)n * K3_PROJ;
        rp[c] = h; rp[D_ + c] = l; rp[2 * D_ + c] = h;
    }
}

// ---------------------------------------------------------------------------
// pack_u3: gate + transpose. (q*v)[b,s,h] -> upack[b][h, 3*2048] B-style.
// grid (S/32, H/32, B), block (32, 8)
// ---------------------------------------------------------------------------
__global__ void pack_u3(const float* __restrict__ q, const float* __restrict__ v,
                        __nv_bfloat16* __restrict__ dst)
{
    __shared__ float tile[32][33];
    const int b  = blockIdx.z;
    const int s0 = blockIdx.x * 32;
    const int h0 = blockIdx.y * 32;
    const long base = (long)b * S_ * H_;
    #pragma unroll
    for (int ry = 0; ry < 4; ++ry) {
        int s = s0 + threadIdx.y + ry * 8;
        long a = base + (long)s * H_ + h0 + threadIdx.x;
        tile[threadIdx.y + ry * 8][threadIdx.x] = q[a] * v[a];
    }
    __syncthreads();
    const long ob = (long)b * H_ * K3_CTX;
    #pragma unroll
    for (int ry = 0; ry < 4; ++ry) {
        int h = h0 + threadIdx.y + ry * 8;
        int s = s0 + threadIdx.x;
        float val = tile[threadIdx.x][threadIdx.y + ry * 8];
        __nv_bfloat16 hh, ll;
        split2(val, hh, ll);
        __nv_bfloat16* rp = dst + ob + (long)h * K3_CTX;
        rp[s] = hh; rp[S_ + s] = ll; rp[2 * S_ + s] = hh;
    }
}

// ---------------------------------------------------------------------------
// Row softmax over 2048 + A-style pack (hi, hi, lo). One block per row.
// ---------------------------------------------------------------------------
__global__ void softmax_pack(const float* __restrict__ sc, __nv_bfloat16* __restrict__ dst)
{
    const int N = 2048;
    const float* row = sc + (size_t)blockIdx.x * N;
    const int t = threadIdx.x;
    float vals[8];
    float m = -1e30f;
    #pragma unroll
    for (int i = 0; i < 8; ++i) {
        vals[i] = row[t + i * 256];
        m = fmaxf(m, vals[i]);
    }
    __shared__ float red[256];
    red[t] = m;
    __syncthreads();
    #pragma unroll
    for (int s = 128; s > 0; s >>= 1) {
        if (t < s) red[t] = fmaxf(red[t], red[t + s]);
        __syncthreads();
    }
    m = red[0];
    __syncthreads();
    float sum = 0.f;
    #pragma unroll
    for (int i = 0; i < 8; ++i) {
        vals[i] = __expf(vals[i] - m);
        sum += vals[i];
    }
    red[t] = sum;
    __syncthreads();
    #pragma unroll
    for (int s = 128; s > 0; s >>= 1) {
        if (t < s) red[t] += red[t + s];
        __syncthreads();
    }
    float inv = 1.0f / red[0];
    __nv_bfloat16* rp = dst + (size_t)blockIdx.x * K3_CTX;
    #pragma unroll
    for (int i = 0; i < 8; ++i) {
        int col = t + i * 256;
        __nv_bfloat16 h, l;
        split2(vals[i] * inv, h, l);
        rp[col] = h; rp[N + col] = h; rp[2 * N + col] = l;
    }
}

// ---------------------------------------------------------------------------
extern "C" void kernel_launch(void* const* d_in, const int* in_sizes, int n_in,
                              void* d_out, int out_size)
{
    const float* x  = (const float*)d_in[0];
    const float* y  = (const float*)d_in[1];
    const float* Wq = (const float*)d_in[2];
    const float* bq = (const float*)d_in[3];
    const float* Wk = (const float*)d_in[4];
    const float* bk = (const float*)d_in[5];
    const float* Wv = (const float*)d_in[6];
    const float* bv = (const float*)d_in[7];
    float* out = (float*)d_out;

    float *q, *v, *sc;
    __nv_bfloat16 *xp, *yp, *wqp, *wkp, *wvp, *qp, *kp, *up, *pp;
    cudaGetSymbolAddress((void**)&q,   g_q);
    cudaGetSymbolAddress((void**)&v,   g_v);
    cudaGetSymbolAddress((void**)&sc,  g_scores);
    cudaGetSymbolAddress((void**)&xp,  g_xpack);
    cudaGetSymbolAddress((void**)&yp,  g_ypack);
    cudaGetSymbolAddress((void**)&wqp, g_wqpack);
    cudaGetSymbolAddress((void**)&wkp, g_wkpack);
    cudaGetSymbolAddress((void**)&wvp, g_wvpack);
    cudaGetSymbolAddress((void**)&qp,  g_qpack);
    cudaGetSymbolAddress((void**)&kp,  g_kpack);
    cudaGetSymbolAddress((void**)&up,  g_upack);
    cudaGetSymbolAddress((void**)&pp,  g_ppack);

    cudaFuncSetAttribute(mm_bf16_kernel<1, true,  true >, cudaFuncAttributeMaxDynamicSharedMemorySize, SMEM_GEMM);
    cudaFuncSetAttribute(mm_bf16_kernel<2, true,  false>, cudaFuncAttributeMaxDynamicSharedMemorySize, SMEM_GEMM);
    cudaFuncSetAttribute(mm_bf16_kernel<0, true,  true >, cudaFuncAttributeMaxDynamicSharedMemorySize, SMEM_GEMM);
    cudaFuncSetAttribute(mm_bf16_kernel<0, false, true >, cudaFuncAttributeMaxDynamicSharedMemorySize, SMEM_GEMM);

    const int M = B_ * S_;   // 16384

    // 1) Input packs (fused: 2 launches total)
    {
        long n4 = (long)M * D_ / 4;
        dim3 ga((unsigned)(n4 / 256), 1, 2);
        pack_ab<<<ga, 256>>>(x, y, xp, yp, n4);
        dim3 gw(H_ / 32, D_ / 32, 3);
        pack_w<<<gw, dim3(32, 8)>>>(Wq, Wk, Wv, wqp, wkp, wvp);
    }

    // 2) Projections, epilogues fuse repacking
    {
        dim3 grid(H_ / 128, M / 128, 1);
        mm_bf16_kernel<1, true, true><<<grid, 256, SMEM_GEMM>>>(
            xp, wqp, bq, q, qp, M, H_, K3_PROJ, 0, 0, 0);
        mm_bf16_kernel<2, true, false><<<grid, 256, SMEM_GEMM>>>(
            xp, wkp, bk, nullptr, kp, M, H_, K3_PROJ, 0, 0, 0);
        mm_bf16_kernel<0, true, true><<<grid, 256, SMEM_GEMM>>>(
            yp, wvp, bv, v, nullptr, M, H_, K3_PROJ, 0, 0, 0);
    }

    // 3) Gate + transpose pack: upack[b] = ((q*v)[b])^T, B-style
    {
        dim3 grid(S_ / 32, H_ / 32, B_);
        pack_u3<<<grid, dim3(32, 8)>>>(q, v, up);
    }

    // 4) Scores: per batch, scores = q @ k^T (fp32 out)
    {
        dim3 grid(S_ / 128, S_ / 128, B_);
        mm_bf16_kernel<0, false, true><<<grid, 256, SMEM_GEMM>>>(
            qp, kp, nullptr, sc, nullptr, S_, S_, K3_PROJ,
            (long)S_ * K3_PROJ, (long)S_ * K3_PROJ, (long)S_ * S_);
    }

    // 5) Softmax + A-style pack of probs
    softmax_pack<<<B_ * S_, 256>>>(sc, pp);

    // 6) Context: per batch, out = probs @ (q*v)
    {
        dim3 grid(H_ / 128, S_ / 128, B_);
        mm_bf16_kernel<0, false, true><<<grid, 256, SMEM_GEMM>>>(
            pp, up, nullptr, out, nullptr, S_, H_, K3_CTX,
            (long)S_ * K3_CTX, (long)H_ * K3_CTX, (long)S_ * H_);
    }
}

// round 15
// speedup vs baseline: 1.5549x; 1.5549x over previous
#include <cuda_runtime.h>
#include <cuda_bf16.h>
#include <cuda_fp16.h>
#include <cstdint>

// ---------------------------------------------------------------------------
// Problem constants
// ---------------------------------------------------------------------------
constexpr int B_ = 8;
constexpr int S_ = 2048;
constexpr int D_ = 768;
constexpr int H_ = 768;
constexpr long QKV_ELEMS = (long)B_ * S_ * H_;   // 12,582,912
constexpr long SC_ELEMS  = (long)B_ * S_ * S_;   // 33,554,432

constexpr int K3_PROJ = 3 * D_;   // 2304  (3-term bf16: q,k proj + scores)
constexpr int K2_VP   = 2 * D_;   // 1536  (2-term fp16: v proj)
constexpr int K2_CTX  = 2 * S_;   // 4096  (2-term fp16: context)

// ---------------------------------------------------------------------------
// Scratch (static device globals — allocation-free per harness rules)
// ---------------------------------------------------------------------------
__device__ float g_q[QKV_ELEMS];
__device__ float g_v[QKV_ELEMS];
__device__ float g_scores[SC_ELEMS];

__device__ __nv_bfloat16 g_xpack [(long)B_*S_*K3_PROJ];   // x 3-term bf16
__device__ __nv_bfloat16 g_wqpack[(long)H_*K3_PROJ];
__device__ __nv_bfloat16 g_wkpack[(long)H_*K3_PROJ];
__device__ __nv_bfloat16 g_qpack [(long)B_*S_*K3_PROJ];   // from q-proj epilogue
__device__ __nv_bfloat16 g_kpack [(long)B_*S_*K3_PROJ];   // from k-proj epilogue
__device__ __half        g_ypack [(long)B_*S_*K2_VP];     // y 2-term fp16
__device__ __half        g_wvpack[(long)H_*K2_VP];        // Wv single fp16, dup
__device__ __half        g_upack [(long)B_*H_*K2_CTX];    // (q*v)^T (uh,ul)
__device__ __half        g_ppack [(long)B_*S_*K2_CTX];    // probs (p,p)

// ---------------------------------------------------------------------------
// PTX helpers (base-target instructions only)
// ---------------------------------------------------------------------------
__device__ __forceinline__ uint32_t smem_to_u32(const void* p) {
    uint32_t a;
    asm("{ .reg .u64 t; cvta.to.shared.u64 t, %1; cvt.u32.u64 %0, t; }"
        : "=r"(a) : "l"(p));
    return a;
}

#define CP_ASYNC16(dst, src) \
    asm volatile("cp.async.cg.shared.global [%0], [%1], 16;" \
                 :: "r"(dst), "l"(src) : "memory")
#define CP_COMMIT() asm volatile("cp.async.commit_group;" ::: "memory")
#define CP_WAIT(n)  asm volatile("cp.async.wait_group %0;" :: "n"(n) : "memory")

#define LDMATRIX_X4(r, addr) \
    asm volatile("ldmatrix.sync.aligned.m8n8.x4.shared.b16 {%0,%1,%2,%3}, [%4];" \
        : "=r"((r)[0]), "=r"((r)[1]), "=r"((r)[2]), "=r"((r)[3]) : "r"(addr))

template<bool F16>
__device__ __forceinline__ void mma16816(float* c, const uint32_t* a,
                                         uint32_t b0, uint32_t b1) {
    if (F16)
        asm volatile(
            "mma.sync.aligned.m16n8k16.row.col.f32.f16.f16.f32 "
            "{%0,%1,%2,%3}, {%4,%5,%6,%7}, {%8,%9}, {%0,%1,%2,%3};"
            : "+f"(c[0]), "+f"(c[1]), "+f"(c[2]), "+f"(c[3])
            : "r"(a[0]), "r"(a[1]), "r"(a[2]), "r"(a[3]), "r"(b0), "r"(b1));
    else
        asm volatile(
            "mma.sync.aligned.m16n8k16.row.col.f32.bf16.bf16.f32 "
            "{%0,%1,%2,%3}, {%4,%5,%6,%7}, {%8,%9}, {%0,%1,%2,%3};"
            : "+f"(c[0]), "+f"(c[1]), "+f"(c[2]), "+f"(c[3])
            : "r"(a[0]), "r"(a[1]), "r"(a[2]), "r"(a[3]), "r"(b0), "r"(b1));
}

// ---------------------------------------------------------------------------
// split helpers
// ---------------------------------------------------------------------------
__device__ __forceinline__ void split2(float x, __nv_bfloat16& h, __nv_bfloat16& l) {
    h = __float2bfloat16(x);
    l = __float2bfloat16(x - __bfloat162float(h));
}
__device__ __forceinline__ uint32_t packpair(__nv_bfloat16 a, __nv_bfloat16 b) {
    __nv_bfloat162 t;
    t.x = a; t.y = b;
    return *reinterpret_cast<uint32_t*>(&t);
}
__device__ __forceinline__ void split2h(float x, __half& h, __half& l) {
    h = __float2half(x);
    l = __float2half(x - __half2float(h));
}
__device__ __forceinline__ uint32_t packpairh(__half a, __half b) {
    __half2 t;
    t.x = a; t.y = b;
    return *reinterpret_cast<uint32_t*>(&t);
}

// ---------------------------------------------------------------------------
// Warp-MMA GEMM: C[M,Ntot] = Apack[M,K3] @ Bpack[Ntot,K3]^T (+bias)
// 256 threads, tile 128x128, warp tile 64x32, BK=32, 4-stage cp.async,
// ONE __syncthreads per k-tile. SMEM rows padded to 80B (conflict-free ldmatrix).
// R8-EXACT mainloop — measured local optimum (216us k-proj @44% tensor); the
// 5-stage (spill) and BK=64 (tensor 34%) probes both regressed. Do not perturb.
// F16: use f16 MMA (operand buffers hold fp16 bits; addressing is typeless).
// PACK: 0=none, 1=A-style (hi,hi,lo), 2=B-style (hi,lo,hi) -> Pout[M,3*Ntot]
// ---------------------------------------------------------------------------
constexpr int STAGES   = 4;
constexpr int BK       = 32;
constexpr int ROWB     = 80;                // 32 elem = 64B + 16B pad
constexpr int OPER_B   = 128 * ROWB;        // 10240 bytes per operand tile
constexpr int STG_B    = 2 * OPER_B;        // 20480 bytes per stage
constexpr int SMEM_GEMM = STAGES * STG_B;   // 81920

template<int PACK, bool BIAS, bool WF32, bool F16>
__global__ __launch_bounds__(256, 2)
void mm_bf16_kernel(const __nv_bfloat16* __restrict__ Apack,
                    const __nv_bfloat16* __restrict__ Bpack,
                    const float* __restrict__ bias,
                    float* __restrict__ C,
                    __nv_bfloat16* __restrict__ Pout,
                    int M, int Ntot, int K3,
                    long sA, long sB, long sC)
{
    extern __shared__ __align__(128) char dsm[];

    const int tid  = threadIdx.x;
    const int wid  = tid >> 5;
    const int lane = tid & 31;
    const long z   = blockIdx.z;
    Apack += z * sA;
    Bpack += z * sB;
    if (WF32) C += z * sC;
    const int brow = blockIdx.y * 128;
    const int bcol = blockIdx.x * 128;

    const int warp_m = (wid >> 2) * 64;   // 0 or 64
    const int warp_n = (wid & 3) * 32;    // 0,32,64,96

    const uint32_t smbase = smem_to_u32(dsm);
    const __nv_bfloat16* Ag = Apack + (long)brow * K3;
    const __nv_bfloat16* Bg = Bpack + (long)bcol * K3;

    // Per-thread load slots: 512 16B-chunks per operand, 2 per thread.
    const int r0 = tid >> 2;          // rows 0..63
    const int ch = tid & 3;           // 16B chunk within row

    auto issue_stage = [&](int s, int k0) {
        uint32_t sa = smbase + s * STG_B;
        #pragma unroll
        for (int i = 0; i < 2; ++i) {
            int r = r0 + i * 64;
            uint32_t d = sa + r * ROWB + ch * 16;
            const __nv_bfloat16* ga = Ag + (long)r * K3 + k0 + ch * 8;
            const __nv_bfloat16* gb = Bg + (long)r * K3 + k0 + ch * 8;
            CP_ASYNC16(d, ga);
            CP_ASYNC16(d + OPER_B, gb);
        }
    };

    float acc[4][4][4];
    #pragma unroll
    for (int i = 0; i < 4; ++i)
        #pragma unroll
        for (int j = 0; j < 4; ++j)
            #pragma unroll
            for (int t = 0; t < 4; ++t) acc[i][j][t] = 0.f;

    const int KT = K3 / BK;
    issue_stage(0, 0);       CP_COMMIT();
    issue_stage(1, BK);      CP_COMMIT();

    // precomputed fragment address components
    const int a_row = lane & 15;
    const int a_kof = (lane >> 4) * 8;
    const int b_row = ((lane >> 4) & 1) * 8 + (lane & 7);
    const int b_kof = ((lane >> 3) & 1) * 8;

    for (int kt = 0; kt < KT; ++kt) {
        // issue next stage (or empty group to keep wait-count invariant)
        if (kt + 2 < KT) issue_stage((kt + 2) & 3, (kt + 2) * BK);
        CP_COMMIT();
        CP_WAIT(2);                 // groups <= kt complete -> stage kt ready
        __syncthreads();            // visibility + overwrite safety (distance 3/4)

        const uint32_t sa = smbase + (kt & 3) * STG_B;
        #pragma unroll
        for (int kk = 0; kk < 2; ++kk) {
            uint32_t a[4][4], b[2][4];
            #pragma unroll
            for (int i = 0; i < 4; ++i) {
                uint32_t addr = sa + (warp_m + i * 16 + a_row) * ROWB
                              + (kk * 16 + a_kof) * 2;
                LDMATRIX_X4(a[i], addr);
            }
            #pragma unroll
            for (int p = 0; p < 2; ++p) {
                uint32_t addr = sa + OPER_B
                              + (warp_n + p * 16 + b_row) * ROWB
                              + (kk * 16 + b_kof) * 2;
                LDMATRIX_X4(b[p], addr);
            }
            #pragma unroll
            for (int i = 0; i < 4; ++i)
                #pragma unroll
                for (int j = 0; j < 4; ++j)
                    mma16816<F16>(acc[i][j], a[i],
                                  b[j >> 1][(j & 1) * 2], b[j >> 1][(j & 1) * 2 + 1]);
        }
    }

    // ---- epilogue ----
    const int rr = lane >> 2;          // 0..7
    const int cc = (lane & 3) * 2;     // 0,2,4,6
    #pragma unroll
    for (int j = 0; j < 4; ++j) {
        const int col = bcol + warp_n + j * 8 + cc;
        float bb0 = 0.f, bb1 = 0.f;
        if (BIAS) { bb0 = bias[col]; bb1 = bias[col + 1]; }
        #pragma unroll
        for (int i = 0; i < 4; ++i) {
            const int row0 = brow + warp_m + i * 16 + rr;
            #pragma unroll
            for (int h = 0; h < 2; ++h) {          // h=0: rows rr, h=1: rr+8
                const int r = row0 + h * 8;
                float v0 = acc[i][j][h * 2 + 0] + bb0;
                float v1 = acc[i][j][h * 2 + 1] + bb1;
                if (WF32) {
                    float2 f2; f2.x = v0; f2.y = v1;
                    *(float2*)(C + (long)r * Ntot + col) = f2;
                }
                if (PACK != 0) {
                    __nv_bfloat16 h0, l0, h1, l1;
                    split2(v0, h0, l0);
                    split2(v1, h1, l1);
                    uint32_t hp = packpair(h0, h1);
                    uint32_t lp = packpair(l0, l1);
                    __nv_bfloat16* rp = Pout + (long)r * 3 * Ntot + col;
                    if (PACK == 1) {   // A-style: hi, hi, lo
                        *(uint32_t*)(rp)            = hp;
                        *(uint32_t*)(rp + Ntot)     = hp;
                        *(uint32_t*)(rp + 2 * Ntot) = lp;
                    } else {           // B-style: hi, lo, hi
                        *(uint32_t*)(rp)            = hp;
                        *(uint32_t*)(rp + Ntot)     = lp;
                        *(uint32_t*)(rp + 2 * Ntot) = hp;
                    }
                }
            }
        }
    }
}

// ---------------------------------------------------------------------------
// pack_x3: x fp32 [R,768] -> bf16 [R,2304] chunks (hi, hi, lo).
// ---------------------------------------------------------------------------
__global__ void pack_x3(const float* __restrict__ src, __nv_bfloat16* __restrict__ dst,
                        long n4)
{
    long i = (long)blockIdx.x * blockDim.x + threadIdx.x;
    if (i >= n4) return;
    float4 f = ((const float4*)src)[i];
    long e = i * 4;
    long r = e / D_;
    int  c = (int)(e % D_);
    __nv_bfloat16 h0, l0, h1, l1, h2, l2, h3, l3;
    split2(f.x, h0, l0); split2(f.y, h1, l1);
    split2(f.z, h2, l2); split2(f.w, h3, l3);
    uint2 hp = make_uint2(packpair(h0, h1), packpair(h2, h3));
    uint2 lp = make_uint2(packpair(l0, l1), packpair(l2, l3));
    __nv_bfloat16* rp = dst + r * (long)K3_PROJ + c;
    *(uint2*)(rp)          = hp;
    *(uint2*)(rp + D_)     = hp;
    *(uint2*)(rp + 2 * D_) = lp;
}

// ---------------------------------------------------------------------------
// pack_y2: y fp32 [R,768] -> fp16 [R,1536] chunks (hi, lo).
// ---------------------------------------------------------------------------
__global__ void pack_y2(const float* __restrict__ src, __half* __restrict__ dst,
                        long n4)
{
    long i = (long)blockIdx.x * blockDim.x + threadIdx.x;
    if (i >= n4) return;
    float4 f = ((const float4*)src)[i];
    long e = i * 4;
    long r = e / D_;
    int  c = (int)(e % D_);
    __half h0, l0, h1, l1, h2, l2, h3, l3;
    split2h(f.x, h0, l0); split2h(f.y, h1, l1);
    split2h(f.z, h2, l2); split2h(f.w, h3, l3);
    uint2 hp = make_uint2(packpairh(h0, h1), packpairh(h2, h3));
    uint2 lp = make_uint2(packpairh(l0, l1), packpairh(l2, l3));
    __half* rp = dst + r * (long)K2_VP + c;
    *(uint2*)(rp)      = hp;
    *(uint2*)(rp + D_) = lp;
}

// ---------------------------------------------------------------------------
// pack_w: Wq/Wk (grid.z selects) [D,H] fp32 -> [H, 3D] bf16 (hi, lo, hi), transposed.
// grid (H/32, D/32, 2), block (32, 8)
// ---------------------------------------------------------------------------
__global__ void pack_w(const float* __restrict__ Wq, const float* __restrict__ Wk,
                       __nv_bfloat16* __restrict__ wqp, __nv_bfloat16* __restrict__ wkp)
{
    const float* W = blockIdx.z == 0 ? Wq : Wk;
    __nv_bfloat16* dst = blockIdx.z == 0 ? wqp : wkp;
    __shared__ float tile[32][33];
    const int n0 = blockIdx.x * 32;
    const int c0 = blockIdx.y * 32;
    #pragma unroll
    for (int ry = 0; ry < 4; ++ry) {
        int c = c0 + threadIdx.y + ry * 8;
        tile[threadIdx.y + ry * 8][threadIdx.x] = W[(long)c * H_ + n0 + threadIdx.x];
    }
    __syncthreads();
    #pragma unroll
    for (int ry = 0; ry < 4; ++ry) {
        int n = n0 + threadIdx.y + ry * 8;
        int c = c0 + threadIdx.x;
        float val = tile[threadIdx.x][threadIdx.y + ry * 8];
        __nv_bfloat16 h, l;
        split2(val, h, l);
        __nv_bfloat16* rp = dst + (long)n * K3_PROJ;
        rp[c] = h; rp[D_ + c] = l; rp[2 * D_ + c] = h;
    }
}

// ---------------------------------------------------------------------------
// pack_wv: Wv [D,H] fp32 -> [H, 2D] fp16 (w, w) duplicated, transposed.
// grid (H/32, D/32), block (32, 8)
// ---------------------------------------------------------------------------
__global__ void pack_wv(const float* __restrict__ W, __half* __restrict__ dst)
{
    __shared__ float tile[32][33];
    const int n0 = blockIdx.x * 32;
    const int c0 = blockIdx.y * 32;
    #pragma unroll
    for (int ry = 0; ry < 4; ++ry) {
        int c = c0 + threadIdx.y + ry * 8;
        tile[threadIdx.y + ry * 8][threadIdx.x] = W[(long)c * H_ + n0 + threadIdx.x];
    }
    __syncthreads();
    #pragma unroll
    for (int ry = 0; ry < 4; ++ry) {
        int n = n0 + threadIdx.y + ry * 8;
        int c = c0 + threadIdx.x;
        __half h = __float2half(tile[threadIdx.x][threadIdx.y + ry * 8]);
        __half* rp = dst + (long)n * K2_VP;
        rp[c] = h; rp[D_ + c] = h;
    }
}

// ---------------------------------------------------------------------------
// pack_u2: gate + transpose. (q*v)[b,s,h] -> upack[b][h, 4096] fp16 (uh, ul).
// grid (S/32, H/32, B), block (32, 8)
// ---------------------------------------------------------------------------
__global__ void pack_u2(const float* __restrict__ q, const float* __restrict__ v,
                        __half* __restrict__ dst)
{
    __shared__ float tile[32][33];
    const int b  = blockIdx.z;
    const int s0 = blockIdx.x * 32;
    const int h0 = blockIdx.y * 32;
    const long base = (long)b * S_ * H_;
    #pragma unroll
    for (int ry = 0; ry < 4; ++ry) {
        int s = s0 + threadIdx.y + ry * 8;
        long a = base + (long)s * H_ + h0 + threadIdx.x;
        tile[threadIdx.y + ry * 8][threadIdx.x] = q[a] * v[a];
    }
    __syncthreads();
    const long ob = (long)b * H_ * K2_CTX;
    #pragma unroll
    for (int ry = 0; ry < 4; ++ry) {
        int h = h0 + threadIdx.y + ry * 8;
        int s = s0 + threadIdx.x;
        float val = tile[threadIdx.x][threadIdx.y + ry * 8];
        __half hh, ll;
        split2h(val, hh, ll);
        __half* rp = dst + ob + (long)h * K2_CTX;
        rp[s] = hh; rp[S_ + s] = ll;
    }
}

// ---------------------------------------------------------------------------
// Row softmax over 2048 + fp16 pack (p, p). One block per row.
// ---------------------------------------------------------------------------
__global__ void softmax_pack(const float* __restrict__ sc, __half* __restrict__ dst)
{
    const int N = 2048;
    const float* row = sc + (size_t)blockIdx.x * N;
    const int t = threadIdx.x;
    float vals[8];
    float m = -1e30f;
    #pragma unroll
    for (int i = 0; i < 8; ++i) {
        vals[i] = row[t + i * 256];
        m = fmaxf(m, vals[i]);
    }
    __shared__ float red[256];
    red[t] = m;
    __syncthreads();
    #pragma unroll
    for (int s = 128; s > 0; s >>= 1) {
        if (t < s) red[t] = fmaxf(red[t], red[t + s]);
        __syncthreads();
    }
    m = red[0];
    __syncthreads();
    float sum = 0.f;
    #pragma unroll
    for (int i = 0; i < 8; ++i) {
        vals[i] = __expf(vals[i] - m);
        sum += vals[i];
    }
    red[t] = sum;
    __syncthreads();
    #pragma unroll
    for (int s = 128; s > 0; s >>= 1) {
        if (t < s) red[t] += red[t + s];
        __syncthreads();
    }
    float inv = 1.0f / red[0];
    __half* rp = dst + (size_t)blockIdx.x * K2_CTX;
    #pragma unroll
    for (int i = 0; i < 8; ++i) {
        int col = t + i * 256;
        __half p = __float2half(vals[i] * inv);
        rp[col] = p; rp[N + col] = p;
    }
}

// ---------------------------------------------------------------------------
extern "C" void kernel_launch(void* const* d_in, const int* in_sizes, int n_in,
                              void* d_out, int out_size)
{
    const float* x  = (const float*)d_in[0];
    const float* y  = (const float*)d_in[1];
    const float* Wq = (const float*)d_in[2];
    const float* bq = (const float*)d_in[3];
    const float* Wk = (const float*)d_in[4];
    const float* bk = (const float*)d_in[5];
    const float* Wv = (const float*)d_in[6];
    const float* bv = (const float*)d_in[7];
    float* out = (float*)d_out;

    float *q, *v, *sc;
    __nv_bfloat16 *xp, *wqp, *wkp, *qp, *kp;
    __half *yp, *wvp, *up, *pp;
    cudaGetSymbolAddress((void**)&q,   g_q);
    cudaGetSymbolAddress((void**)&v,   g_v);
    cudaGetSymbolAddress((void**)&sc,  g_scores);
    cudaGetSymbolAddress((void**)&xp,  g_xpack);
    cudaGetSymbolAddress((void**)&wqp, g_wqpack);
    cudaGetSymbolAddress((void**)&wkp, g_wkpack);
    cudaGetSymbolAddress((void**)&qp,  g_qpack);
    cudaGetSymbolAddress((void**)&kp,  g_kpack);
    cudaGetSymbolAddress((void**)&yp,  g_ypack);
    cudaGetSymbolAddress((void**)&wvp, g_wvpack);
    cudaGetSymbolAddress((void**)&up,  g_upack);
    cudaGetSymbolAddress((void**)&pp,  g_ppack);

    cudaFuncSetAttribute(mm_bf16_kernel<1, true,  true,  false>, cudaFuncAttributeMaxDynamicSharedMemorySize, SMEM_GEMM);
    cudaFuncSetAttribute(mm_bf16_kernel<2, true,  false, false>, cudaFuncAttributeMaxDynamicSharedMemorySize, SMEM_GEMM);
    cudaFuncSetAttribute(mm_bf16_kernel<0, true,  true,  true >, cudaFuncAttributeMaxDynamicSharedMemorySize, SMEM_GEMM);
    cudaFuncSetAttribute(mm_bf16_kernel<0, false, true,  false>, cudaFuncAttributeMaxDynamicSharedMemorySize, SMEM_GEMM);
    cudaFuncSetAttribute(mm_bf16_kernel<0, false, true,  true >, cudaFuncAttributeMaxDynamicSharedMemorySize, SMEM_GEMM);

    const int M = B_ * S_;   // 16384

    // 1) Input packs
    {
        long n4 = (long)M * D_ / 4;
        pack_x3<<<(unsigned)(n4 / 256), 256>>>(x, xp, n4);
        pack_y2<<<(unsigned)(n4 / 256), 256>>>(y, yp, n4);
        dim3 gw(H_ / 32, D_ / 32, 2);
        pack_w<<<gw, dim3(32, 8)>>>(Wq, Wk, wqp, wkp);
        dim3 gv(H_ / 32, D_ / 32);
        pack_wv<<<gv, dim3(32, 8)>>>(Wv, wvp);
    }

    // 2) Projections (q,k: 3-term bf16 w/ fused repack; v: 2-term fp16)
    {
        dim3 grid(H_ / 128, M / 128, 1);
        mm_bf16_kernel<1, true, true, false><<<grid, 256, SMEM_GEMM>>>(
            xp, wqp, bq, q, qp, M, H_, K3_PROJ, 0, 0, 0);
        mm_bf16_kernel<2, true, false, false><<<grid, 256, SMEM_GEMM>>>(
            xp, wkp, bk, nullptr, kp, M, H_, K3_PROJ, 0, 0, 0);
        mm_bf16_kernel<0, true, true, true><<<grid, 256, SMEM_GEMM>>>(
            (const __nv_bfloat16*)yp, (const __nv_bfloat16*)wvp, bv, v, nullptr,
            M, H_, K2_VP, 0, 0, 0);
    }

    // 3) Gate + transpose pack: upack[b] = ((q*v)[b])^T, fp16 (uh,ul)
    {
        dim3 grid(S_ / 32, H_ / 32, B_);
        pack_u2<<<grid, dim3(32, 8)>>>(q, v, up);
    }

    // 4) Scores: per batch, scores = q @ k^T (3-term bf16, fp32 out)
    {
        dim3 grid(S_ / 128, S_ / 128, B_);
        mm_bf16_kernel<0, false, true, false><<<grid, 256, SMEM_GEMM>>>(
            qp, kp, nullptr, sc, nullptr, S_, S_, K3_PROJ,
            (long)S_ * K3_PROJ, (long)S_ * K3_PROJ, (long)S_ * S_);
    }

    // 5) Softmax + fp16 pack of probs
    softmax_pack<<<B_ * S_, 256>>>(sc, pp);

    // 6) Context: per batch, out = probs @ (q*v)  (2-term fp16)
    {
        dim3 grid(H_ / 128, S_ / 128, B_);
        mm_bf16_kernel<0, false, true, true><<<grid, 256, SMEM_GEMM>>>(
            (const __nv_bfloat16*)pp, (const __nv_bfloat16*)up, nullptr, out, nullptr,
            S_, H_, K2_CTX,
            (long)S_ * K2_CTX, (long)H_ * K2_CTX, (long)S_ * H_);
    }
}